// round 14
// baseline (speedup 1.0000x reference)
#include <cuda_runtime.h>
#include <cuda_bf16.h>
#include <cstdint>

#define NB     32
#define NPTS   2048
#define TPB    128
#define NWARP  (TPB / 32)
#define RTILES 16
#define ROWS   (NPTS / RTILES)          // 128 rows per block (== TPB)
#define CPP    8                        // packed col-pairs per thread (16 cols)
#define CHUNK  32                       // rows per transpose-reduce chunk
#define BIGSQ  1.0e16f

// Packed f32x2 ops (sm_103a — PTX-only)
#define FMA_F32X2(d, a, b, c) \
    asm("fma.rn.f32x2 %0, %1, %2, %3;" : "=l"(d) : "l"(a), "l"(b), "l"(c))
#define ADD_F32X2(d, a, b) \
    asm("add.rn.f32x2 %0, %1, %2;" : "=l"(d) : "l"(a), "l"(b))

__device__ __forceinline__ unsigned long long pack2(float lo, float hi) {
    unsigned long long r;
    asm("mov.b64 %0, {%1, %2};" : "=l"(r) : "f"(lo), "f"(hi));
    return r;
}
__device__ __forceinline__ void unpack2(float& lo, float& hi, unsigned long long v) {
    asm("mov.b64 {%0, %1}, %2;" : "=f"(lo), "=f"(hi) : "l"(v));
}

// scratch: col-min partials [b][tile][col], row-sums [b][tile], tickets
__device__ float g_colmin[NB * RTILES * NPTS];
__device__ float g_rowsum[NB * RTILES];
__device__ int   g_ticket[NB];          // zero-init; reset by consumer each launch

__global__ __launch_bounds__(TPB) void chamfer_kernel(
    const int*   __restrict__ o_w,   const float* __restrict__ o_pts,
    const int*   __restrict__ t_w,   const float* __restrict__ t_pts,
    float*       __restrict__ out)
{
    const int b    = blockIdx.x;
    const int tile = blockIdx.y;
    const int tid  = threadIdx.x;
    const int wid  = tid >> 5;
    const int lane = tid & 31;
    const int row0 = tile * ROWS;

    __shared__ ulonglong2 sA[ROWS];               // (m2x,m2x | m2y,m2y)
    __shared__ ulonglong2 sB[ROWS];               // (m2z,m2z | r2,r2)
    __shared__ float sPM[NWARP][CHUNK][33];       // per-warp row candidates (padded)
    __shared__ float rowpart[NWARP][ROWS];        // per-warp row mins
    __shared__ int   s_last;

    // ---- stage rows: 1 row per thread (TPB == ROWS) ----
    {
        int n = row0 + tid;
        const float* p = o_pts + ((size_t)b * NPTS + n) * 3;
        int w = o_w[b * NPTS + n];
        float x = p[0], y = p[1], z = p[2];
        float r2 = x * x + y * y + z * z;
        float mx = -2.0f * x, my = -2.0f * y, mz = -2.0f * z;
        if (!w) { mx = 0.f; my = 0.f; mz = 0.f; r2 = BIGSQ; }  // masked row can't win col-mins
        ulonglong2 va, vb;
        va.x = pack2(mx, mx);  va.y = pack2(my, my);
        vb.x = pack2(mz, mz);  vb.y = pack2(r2, r2);
        sA[tid] = va;  sB[tid] = vb;
    }

    // ---- thread-owned columns: 8 packed pairs = 16 cols ----
    unsigned long long X[CPP], Y[CPP], Z[CPP], C2[CPP];
    float cmlo[CPP], cmhi[CPP];
    #pragma unroll
    for (int p = 0; p < CPP; p++) {
        int j  = tid + p * TPB;                   // pair index 0..1023
        int c0 = 2 * j;
        const float* q = t_pts + ((size_t)b * NPTS + c0) * 3;
        int w0 = t_w[b * NPTS + c0];
        int w1 = t_w[b * NPTS + c0 + 1];
        float x0 = q[0], y0 = q[1], z0 = q[2];
        float x1 = q[3], y1 = q[4], z1 = q[5];
        if (!w0) { x0 = 0.f; y0 = 0.f; z0 = 0.f; }
        if (!w1) { x1 = 0.f; y1 = 0.f; z1 = 0.f; }
        float c0s = w0 ? (x0*x0 + y0*y0 + z0*z0) : BIGSQ;  // masked col can't win row-mins
        float c1s = w1 ? (x1*x1 + y1*y1 + z1*z1) : BIGSQ;
        X[p]  = pack2(x0, x1);
        Y[p]  = pack2(y0, y1);
        Z[p]  = pack2(z0, z1);
        C2[p] = pack2(c0s, c1s);
        cmlo[p] = 3.4e38f;  cmhi[p] = 3.4e38f;
    }

    __syncthreads();

    // ---- stream rows in chunks of 32; transpose-reduce, no shuffles ----
    for (int chunk = 0; chunk < ROWS / CHUNK; chunk++) {
        #pragma unroll 2
        for (int rr = 0; rr < CHUNK; rr++) {
            const int r = chunk * CHUNK + rr;
            const ulonglong2 va = sA[r];
            const ulonglong2 vb = sB[r];
            float pm[CPP];
            #pragma unroll
            for (int p = 0; p < CPP; p++) {
                unsigned long long v;
                ADD_F32X2(v, C2[p], vb.y);          // c^2 + r^2
                FMA_F32X2(v, va.x, X[p], v);        // - 2 x_r x_c
                FMA_F32X2(v, va.y, Y[p], v);
                FMA_F32X2(v, vb.x, Z[p], v);
                float v0, v1;
                unpack2(v0, v1, v);
                cmlo[p] = fminf(cmlo[p], v0);       // col mins (lane-local)
                cmhi[p] = fminf(cmhi[p], v1);
                pm[p]   = fminf(v0, v1);
            }
            float t0 = fminf(fminf(pm[0], pm[1]), fminf(pm[2], pm[3]));
            float t1 = fminf(fminf(pm[4], pm[5]), fminf(pm[6], pm[7]));
            sPM[wid][rr][lane] = fminf(t0, t1);
        }
        __syncwarp();
        // transpose-reduce: lane l reduces row (chunk*32 + l); 4 parallel chains
        {
            const float* src = sPM[wid][lane];
            float a0 = src[0], a1 = src[1], a2 = src[2], a3 = src[3];
            #pragma unroll
            for (int j = 4; j < 32; j += 4) {
                a0 = fminf(a0, src[j]);
                a1 = fminf(a1, src[j + 1]);
                a2 = fminf(a2, src[j + 2]);
                a3 = fminf(a3, src[j + 3]);
            }
            rowpart[wid][chunk * CHUNK + lane] = fminf(fminf(a0, a1), fminf(a2, a3));
        }
        __syncwarp();
    }

    // ---- col-min partials -> global scratch ----
    float* cm = g_colmin + ((size_t)b * RTILES + tile) * NPTS;
    #pragma unroll
    for (int p = 0; p < CPP; p++) {
        int c0 = 2 * (tid + p * TPB);
        cm[c0]     = cmlo[p];
        cm[c0 + 1] = cmhi[p];
    }

    __syncthreads();

    // ---- row-side finish: merge warp partials, clamp, mask, sum over tile ----
    {
        float mn = rowpart[0][tid];
        #pragma unroll
        for (int w = 1; w < NWARP; w++) mn = fminf(mn, rowpart[w][tid]);
        float wr  = (float)o_w[b * NPTS + row0 + tid];
        float acc = fmaxf(mn, 0.0f) * wr;

        __shared__ float red[NWARP];
        #pragma unroll
        for (int o = 16; o > 0; o >>= 1)
            acc += __shfl_down_sync(0xffffffffu, acc, o);
        if (lane == 0) red[wid] = acc;
        __syncthreads();
        if (tid == 0) {
            float rs = 0.0f;
            #pragma unroll
            for (int w = 0; w < NWARP; w++) rs += red[w];
            g_rowsum[b * RTILES + tile] = rs;
        }
    }

    // ---- decoupled last-block reduction for this batch ----
    __threadfence();
    __syncthreads();
    if (tid == 0) s_last = atomicAdd(&g_ticket[b], 1);
    __syncthreads();
    if (s_last != RTILES - 1) return;

    __threadfence();
    const float* cmb = g_colmin + (size_t)b * RTILES * NPTS;
    float acc = 0.0f;
    #pragma unroll
    for (int k = 0; k < NPTS / TPB; k++) {
        int c = tid + k * TPB;
        float mn = cmb[c];
        #pragma unroll
        for (int t = 1; t < RTILES; t++) mn = fminf(mn, cmb[t * NPTS + c]);
        float wc = (float)t_w[b * NPTS + c];
        acc += fmaxf(mn, 0.0f) * wc;
    }

    __shared__ float red2[NWARP];
    #pragma unroll
    for (int o = 16; o > 0; o >>= 1)
        acc += __shfl_down_sync(0xffffffffu, acc, o);
    if (lane == 0) red2[wid] = acc;
    __syncthreads();
    if (tid == 0) {
        float s = 0.0f;
        #pragma unroll
        for (int w = 0; w < NWARP; w++) s += red2[w];
        float rs = 0.0f;
        #pragma unroll
        for (int t = 0; t < RTILES; t++) rs += g_rowsum[b * RTILES + t];
        out[b] = 0.5f * (rs + s);
        g_ticket[b] = 0;                 // reset for next graph replay
    }
}

extern "C" void kernel_launch(void* const* d_in, const int* in_sizes, int n_in,
                              void* d_out, int out_size) {
    const int*   o_w   = (const int*)  d_in[0];
    const float* o_pts = (const float*)d_in[1];
    const int*   t_w   = (const int*)  d_in[2];
    const float* t_pts = (const float*)d_in[3];
    float* out = (float*)d_out;

    dim3 grid(NB, RTILES);                       // 512 blocks, single launch
    chamfer_kernel<<<grid, TPB>>>(o_w, o_pts, t_w, t_pts, out);
}

// round 15
// speedup vs baseline: 1.1113x; 1.1113x over previous
#include <cuda_runtime.h>
#include <cuda_bf16.h>
#include <cstdint>

#define NB     32
#define NPTS   2048
#define TPB    256
#define NWARP  (TPB / 32)
#define RTILES 16
#define ROWS   (NPTS / RTILES)          // 128 rows per block
#define CPP    4                        // packed col-pairs per thread (8 cols)
#define CHUNK  16                       // rows per transpose-reduce chunk
#define BIGSQ  1.0e16f

// Packed f32x2 ops (sm_103a — PTX-only)
#define FMA_F32X2(d, a, b, c) \
    asm("fma.rn.f32x2 %0, %1, %2, %3;" : "=l"(d) : "l"(a), "l"(b), "l"(c))
#define ADD_F32X2(d, a, b) \
    asm("add.rn.f32x2 %0, %1, %2;" : "=l"(d) : "l"(a), "l"(b))

__device__ __forceinline__ unsigned long long pack2(float lo, float hi) {
    unsigned long long r;
    asm("mov.b64 %0, {%1, %2};" : "=l"(r) : "f"(lo), "f"(hi));
    return r;
}
__device__ __forceinline__ void unpack2(float& lo, float& hi, unsigned long long v) {
    asm("mov.b64 {%0, %1}, %2;" : "=f"(lo), "=f"(hi) : "l"(v));
}

// scratch: col-min partials [b][tile][col], row-sums [b][tile], tickets
__device__ float g_colmin[NB * RTILES * NPTS];
__device__ float g_rowsum[NB * RTILES];
__device__ int   g_ticket[NB];          // zero-init; reset by consumer each launch

__global__ __launch_bounds__(TPB) void chamfer_kernel(
    const int*   __restrict__ o_w,   const float* __restrict__ o_pts,
    const int*   __restrict__ t_w,   const float* __restrict__ t_pts,
    float*       __restrict__ out)
{
    const int b    = blockIdx.x;
    const int tile = blockIdx.y;
    const int tid  = threadIdx.x;
    const int wid  = tid >> 5;
    const int lane = tid & 31;
    const int row0 = tile * ROWS;

    __shared__ ulonglong2 sA[ROWS];               // (m2x,m2x | m2y,m2y)
    __shared__ ulonglong2 sB[ROWS];               // (m2z,m2z | r2,r2)
    __shared__ float sPM[NWARP][CHUNK][33];       // per-warp row candidates
    __shared__ float rowpart[NWARP][ROWS];        // per-warp row mins
    __shared__ int   s_last;

    // ---- stage rows (128 rows, 256 threads) ----
    if (tid < ROWS) {
        int n = row0 + tid;
        const float* p = o_pts + ((size_t)b * NPTS + n) * 3;
        int w = o_w[b * NPTS + n];
        float x = p[0], y = p[1], z = p[2];
        float r2 = x * x + y * y + z * z;
        float mx = -2.0f * x, my = -2.0f * y, mz = -2.0f * z;
        if (!w) { mx = 0.f; my = 0.f; mz = 0.f; r2 = BIGSQ; }  // masked row can't win col-mins
        ulonglong2 va, vb;
        va.x = pack2(mx, mx);  va.y = pack2(my, my);
        vb.x = pack2(mz, mz);  vb.y = pack2(r2, r2);
        sA[tid] = va;  sB[tid] = vb;
    }

    // ---- thread-owned columns: 4 packed pairs = 8 cols ----
    unsigned long long X[CPP], Y[CPP], Z[CPP], C2[CPP];
    float cmlo[CPP], cmhi[CPP];
    #pragma unroll
    for (int p = 0; p < CPP; p++) {
        int j  = tid + p * TPB;
        int c0 = 2 * j;
        const float* q = t_pts + ((size_t)b * NPTS + c0) * 3;
        int w0 = t_w[b * NPTS + c0];
        int w1 = t_w[b * NPTS + c0 + 1];
        float x0 = q[0], y0 = q[1], z0 = q[2];
        float x1 = q[3], y1 = q[4], z1 = q[5];
        if (!w0) { x0 = 0.f; y0 = 0.f; z0 = 0.f; }
        if (!w1) { x1 = 0.f; y1 = 0.f; z1 = 0.f; }
        float c0s = w0 ? (x0*x0 + y0*y0 + z0*z0) : BIGSQ;  // masked col can't win row-mins
        float c1s = w1 ? (x1*x1 + y1*y1 + z1*z1) : BIGSQ;
        X[p]  = pack2(x0, x1);
        Y[p]  = pack2(y0, y1);
        Z[p]  = pack2(z0, z1);
        C2[p] = pack2(c0s, c1s);
        cmlo[p] = 3.4e38f;  cmhi[p] = 3.4e38f;
    }

    __syncthreads();

    // ---- stream rows: 2-row bodies (8 independent FMA chains each) ----
    for (int chunk = 0; chunk < ROWS / CHUNK; chunk++) {
        #pragma unroll 2
        for (int g = 0; g < CHUNK / 2; g++) {
            const int r0 = chunk * CHUNK + 2 * g;
            const ulonglong2 va0 = sA[r0],     vb0 = sB[r0];
            const ulonglong2 va1 = sA[r0 + 1], vb1 = sB[r0 + 1];
            float pm0[CPP], pm1[CPP];
            #pragma unroll
            for (int p = 0; p < CPP; p++) {
                unsigned long long v0, v1;
                FMA_F32X2(v0, va0.x, X[p], vb0.y);   // r2 - 2ax
                FMA_F32X2(v0, va0.y, Y[p], v0);
                FMA_F32X2(v0, vb0.x, Z[p], v0);
                ADD_F32X2(v0, v0, C2[p]);            // + c2
                FMA_F32X2(v1, va1.x, X[p], vb1.y);
                FMA_F32X2(v1, va1.y, Y[p], v1);
                FMA_F32X2(v1, vb1.x, Z[p], v1);
                ADD_F32X2(v1, v1, C2[p]);
                float a0, a1, b0, b1;
                unpack2(a0, a1, v0);
                unpack2(b0, b1, v1);
                // col mins: combine the two rows first (halves chain depth)
                cmlo[p] = fminf(cmlo[p], fminf(a0, b0));
                cmhi[p] = fminf(cmhi[p], fminf(a1, b1));
                // row candidates
                pm0[p] = fminf(a0, a1);
                pm1[p] = fminf(b0, b1);
            }
            sPM[wid][2 * g][lane]     = fminf(fminf(pm0[0], pm0[1]), fminf(pm0[2], pm0[3]));
            sPM[wid][2 * g + 1][lane] = fminf(fminf(pm1[0], pm1[1]), fminf(pm1[2], pm1[3]));
        }
        __syncwarp();
        // transpose-reduce: 16 rows x 32 lane-candidates; two half-lanes + shfl merge
        {
            const int row  = lane & 15;
            const int half = lane >> 4;
            const float* src = &sPM[wid][row][half * 16];
            float a0 = src[0], a1 = src[1], a2 = src[2], a3 = src[3];
            #pragma unroll
            for (int j = 4; j < 16; j += 4) {
                a0 = fminf(a0, src[j]);
                a1 = fminf(a1, src[j + 1]);
                a2 = fminf(a2, src[j + 2]);
                a3 = fminf(a3, src[j + 3]);
            }
            float m = fminf(fminf(a0, a1), fminf(a2, a3));
            float o = __shfl_xor_sync(0xffffffffu, m, 16);
            m = fminf(m, o);
            if (lane < 16) rowpart[wid][chunk * CHUNK + row] = m;
        }
        __syncwarp();
    }

    // ---- col-min partials -> global scratch ----
    float* cm = g_colmin + ((size_t)b * RTILES + tile) * NPTS;
    #pragma unroll
    for (int p = 0; p < CPP; p++) {
        int c0 = 2 * (tid + p * TPB);
        cm[c0]     = cmlo[p];
        cm[c0 + 1] = cmhi[p];
    }

    __syncthreads();

    // ---- row-side finish: merge warp partials, clamp, mask, sum over tile ----
    {
        float acc = 0.0f;
        if (tid < ROWS) {
            float mn = rowpart[0][tid];
            #pragma unroll
            for (int w = 1; w < NWARP; w++) mn = fminf(mn, rowpart[w][tid]);
            float wr = (float)o_w[b * NPTS + row0 + tid];
            acc = fmaxf(mn, 0.0f) * wr;
        }
        __shared__ float red[NWARP];
        #pragma unroll
        for (int o = 16; o > 0; o >>= 1)
            acc += __shfl_down_sync(0xffffffffu, acc, o);
        if (lane == 0) red[wid] = acc;
        __syncthreads();
        if (tid == 0) {
            float rs = 0.0f;
            #pragma unroll
            for (int w = 0; w < NWARP; w++) rs += red[w];
            g_rowsum[b * RTILES + tile] = rs;
        }
    }

    // ---- decoupled last-block reduction for this batch ----
    __threadfence();
    __syncthreads();
    if (tid == 0) s_last = atomicAdd(&g_ticket[b], 1);
    __syncthreads();
    if (s_last != RTILES - 1) return;

    __threadfence();
    const float* cmb = g_colmin + (size_t)b * RTILES * NPTS;
    float acc = 0.0f;
    #pragma unroll
    for (int k = 0; k < NPTS / TPB; k++) {
        int c = tid + k * TPB;
        float mn = cmb[c];
        #pragma unroll
        for (int t = 1; t < RTILES; t++) mn = fminf(mn, cmb[t * NPTS + c]);
        float wc = (float)t_w[b * NPTS + c];
        acc += fmaxf(mn, 0.0f) * wc;
    }

    __shared__ float red2[NWARP];
    #pragma unroll
    for (int o = 16; o > 0; o >>= 1)
        acc += __shfl_down_sync(0xffffffffu, acc, o);
    if (lane == 0) red2[wid] = acc;
    __syncthreads();
    if (tid == 0) {
        float s = 0.0f;
        #pragma unroll
        for (int w = 0; w < NWARP; w++) s += red2[w];
        float rs = 0.0f;
        #pragma unroll
        for (int t = 0; t < RTILES; t++) rs += g_rowsum[b * RTILES + t];
        out[b] = 0.5f * (rs + s);
        g_ticket[b] = 0;                 // reset for next graph replay
    }
}

extern "C" void kernel_launch(void* const* d_in, const int* in_sizes, int n_in,
                              void* d_out, int out_size) {
    const int*   o_w   = (const int*)  d_in[0];
    const float* o_pts = (const float*)d_in[1];
    const int*   t_w   = (const int*)  d_in[2];
    const float* t_pts = (const float*)d_in[3];
    float* out = (float*)d_out;

    dim3 grid(NB, RTILES);                       // 512 blocks, single launch
    chamfer_kernel<<<grid, TPB>>>(o_w, o_pts, t_w, t_pts, out);
}